// round 6
// baseline (speedup 1.0000x reference)
#include <cuda_runtime.h>

// PlasticNet: T=64 steps, B=32, I=128, H=256, clip=2.0
// out = [ ys (T*B*H) | h_f (B*H) | hebb_f (B*H*H) ]  float32
//
// 32 clusters of 4 CTAs (one per sample). CTA c owns presynaptic rows
// [c*64, c*64+64). Thread t owns column t: 64 hebb/w/alpha scalars in regs,
// packed as 32 f32x2 pairs (fma.rn.f32x2; clip scalar on the halves).
// Per step: push 256-wide rec partials to peers via DSMEM, then a 4-arrival
// cluster mbarrier (release/acquire, double buffered) orders delivery.

static constexpr int kT = 64;
static constexpr int kB = 32;
static constexpr int kI = 128;
static constexpr int kH = 256;
static constexpr int kRows = 64;
static constexpr int kNCTA = kB * 4;
static constexpr int kThreads = 256;

typedef unsigned long long ull;

__device__ float g_xwi[kT * kB * kH];              // x@Wi + bi, precomputed

// ---------------------------------------------------------------------------
__global__ void xwi_kernel(const float* __restrict__ x,
                           const float* __restrict__ Wi,
                           const float* __restrict__ bi) {
    __shared__ float xs[kI];
    const int row = blockIdx.x;        // 0 .. T*B-1
    const int k = threadIdx.x;         // 0 .. 255
    if (k < kI) xs[k] = x[row * kI + k];
    __syncthreads();
    float acc = bi[k];
#pragma unroll 16
    for (int i = 0; i < kI; ++i)
        acc = fmaf(xs[i], Wi[i * kH + k], acc);
    g_xwi[row * kH + k] = acc;
}

// ---------------------------------------------------------------------------
// PTX helpers
// ---------------------------------------------------------------------------
__device__ __forceinline__ unsigned smem_u32(const void* p) {
    return (unsigned)__cvta_generic_to_shared(p);
}
__device__ __forceinline__ unsigned mapa_u32(unsigned addr, unsigned rank) {
    unsigned o;
    asm("mapa.shared::cluster.u32 %0, %1, %2;" : "=r"(o) : "r"(addr), "r"(rank));
    return o;
}
__device__ __forceinline__ void st_cluster_f32(unsigned addr, float v) {
    asm volatile("st.shared::cluster.f32 [%0], %1;" :: "r"(addr), "f"(v) : "memory");
}
__device__ __forceinline__ void mbar_init(unsigned addr, unsigned cnt) {
    asm volatile("mbarrier.init.shared.b64 [%0], %1;" :: "r"(addr), "r"(cnt) : "memory");
}
__device__ __forceinline__ void mbar_arrive_rel_cluster(unsigned addr) {
    asm volatile("mbarrier.arrive.release.cluster.shared::cluster.b64 _, [%0];"
                 :: "r"(addr) : "memory");
}
__device__ __forceinline__ void mbar_wait_acq_cluster(unsigned addr, unsigned phase) {
    unsigned done;
    asm volatile(
        "{\n\t.reg .pred p;\n\t"
        "mbarrier.try_wait.parity.acquire.cluster.shared::cta.b64 p, [%1], %2;\n\t"
        "selp.b32 %0, 1, 0, p;\n\t}"
        : "=r"(done) : "r"(addr), "r"(phase) : "memory");
    if (!done) {
        asm volatile(
            "{\n\t.reg .pred P1;\n\t"
            "W_%=:\n\t"
            "mbarrier.try_wait.parity.acquire.cluster.shared::cta.b64 P1, [%0], %1, 0x989680;\n\t"
            "@P1 bra.uni D_%=;\n\t"
            "bra.uni W_%=;\n\t"
            "D_%=:\n\t}"
            :: "r"(addr), "r"(phase) : "memory");
    }
}
__device__ __forceinline__ void cluster_sync_all() {
    asm volatile("barrier.cluster.arrive.aligned;" ::: "memory");
    asm volatile("barrier.cluster.wait.aligned;" ::: "memory");
}

// ---- f32x2 packed math (PTX has fma/add/mul only; clip done on halves) ----
__device__ __forceinline__ ull pack2(float lo, float hi) {
    ull r; asm("mov.b64 %0, {%1, %2};" : "=l"(r) : "f"(lo), "f"(hi)); return r;
}
__device__ __forceinline__ void unpack2(ull v, float& lo, float& hi) {
    asm("mov.b64 {%0, %1}, %2;" : "=f"(lo), "=f"(hi) : "l"(v));
}
__device__ __forceinline__ ull fma2(ull a, ull b, ull c) {
    ull d; asm("fma.rn.f32x2 %0, %1, %2, %3;" : "=l"(d) : "l"(a), "l"(b), "l"(c));
    return d;
}
__device__ __forceinline__ ull clip2(ull v) {
    float lo, hi;
    unpack2(v, lo, hi);
    lo = fminf(fmaxf(lo, -2.f), 2.f);
    hi = fminf(fmaxf(hi, -2.f), 2.f);
    return pack2(lo, hi);
}

// ---------------------------------------------------------------------------
__global__ void __launch_bounds__(kThreads, 1) __cluster_dims__(4, 1, 1)
plastic_kernel(const float* __restrict__ w,
               const float* __restrict__ alpha,
               const float* __restrict__ Wm,
               const float* __restrict__ bm,
               const float* __restrict__ Wf,
               const float* __restrict__ bf,
               float* __restrict__ out) {
    const int b = blockIdx.x >> 2;
    const int c = blockIdx.x & 3;      // cluster ctarank
    const int t = threadIdx.x;
    const int lane = t & 31;
    const int wid = t >> 5;
    const int i0 = c * kRows;

    // Register state, packed by presynaptic-row pairs: pair j = rows i0+2j, i0+2j+1
    ull wv2[32], av2[32], hb2[32];
#pragma unroll
    for (int j = 0; j < 32; ++j) {
        wv2[j] = pack2(__ldg(&w[(i0 + 2 * j) * kH + t]),
                       __ldg(&w[(i0 + 2 * j + 1) * kH + t]));
        av2[j] = pack2(__ldg(&alpha[(i0 + 2 * j) * kH + t]),
                       __ldg(&alpha[(i0 + 2 * j + 1) * kH + t]));
        hb2[j] = 0ull;
    }
    const float wf_t = __ldg(&Wf[t]);
    const float bf_t = __ldg(&bf[t]);
    const float wm_t = __ldg(&Wm[t]);
    const float bm0 = __ldg(&bm[0]);

    __shared__ __align__(16) float hbuf[2][kH];       // h double buffer
    __shared__ __align__(16) float recv[2][4][kH];    // cluster partials, dbl buf
    __shared__ __align__(16) float wpart[8];          // per-warp eta partials
    __shared__ __align__(8) unsigned long long mbar[2];

    if (t == 0) { mbar_init(smem_u32(&mbar[0]), 4); mbar_init(smem_u32(&mbar[1]), 4); }
    hbuf[0][t] = 0.f;   // h_{-1} = 0
    __syncthreads();
    cluster_sync_all();   // peers' smem + mbarriers live before any remote op

    // DSMEM addresses: partial pushes (3 peers) and barrier arrives (4 CTAs)
    unsigned pr_addr[2][3], mb_addr[2][4];
#pragma unroll
    for (int p = 0; p < 2; ++p) {
        const unsigned lr = smem_u32(&recv[p][c][t]);
        const unsigned lm = smem_u32(&mbar[p]);
#pragma unroll
        for (int d = 1; d < 4; ++d)
            pr_addr[p][d - 1] = mapa_u32(lr, (unsigned)((c + d) & 3));
#pragma unroll
        for (int d = 0; d < 4; ++d)
            mb_addr[p][d] = mapa_u32(lm, (unsigned)((c + d) & 3));
    }

    float* __restrict__ ys = out;
    float* __restrict__ hf = out + kT * kB * kH;
    float* __restrict__ hebbf = out + kT * kB * kH + kB * kH;

    // step 0: h_{-1}=0 -> rec=0 -> h = tanh(xwi[0])
    float h_cur = tanhf(__ldg(&g_xwi[b * kH + t]));

    for (int step = 0; step < kT; ++step) {
        const int par = step & 1;
        const float* __restrict__ hp = hbuf[par];        // h_{step-1}
        float* __restrict__ hn = hbuf[par ^ 1];          // h_step

        // prefetch next step's xwi a full step early
        float xw_next = 0.f;
        if (step < kT - 1)
            xw_next = __ldg(&g_xwi[((step + 1) * kB + b) * kH + t]);

        hn[t] = h_cur;
        // eta partial: warp-level reduce of h.Wm, pre-sync
        float s = h_cur * wm_t;
#pragma unroll
        for (int off = 16; off; off >>= 1)
            s += __shfl_xor_sync(0xffffffffu, s, off);
        if (lane == 0) wpart[wid] = s;
        if (c == 0) ys[(step * kB + b) * kH + t] = h_cur;
        __syncthreads();

        // ---- eta = tanh(h . Wm + bm) ----
        const float4 wp0 = *reinterpret_cast<const float4*>(&wpart[0]);
        const float4 wp1 = *reinterpret_cast<const float4*>(&wpart[4]);
        const float eta = tanhf(((wp0.x + wp0.y) + (wp0.z + wp0.w)) +
                                ((wp1.x + wp1.y) + (wp1.z + wp1.w)) + bm0);
        const float v = fmaf(eta, wf_t, bf_t) * h_cur;    // me_t * h_t
        const ull vv = pack2(v, v);

        // ---- fused sweep: hebb = clip(hebb + v*hp), pr += hn*(w + a*hebb) ----
        ull prA = 0ull, prB = 0ull;
#pragma unroll
        for (int jj = 0; jj < 16; ++jj) {
            const float4 hp4 = *reinterpret_cast<const float4*>(&hp[i0 + 4 * jj]);
            const float4 hn4 = *reinterpret_cast<const float4*>(&hn[i0 + 4 * jj]);
            const ull hpa = pack2(hp4.x, hp4.y), hpb = pack2(hp4.z, hp4.w);
            const ull hna = pack2(hn4.x, hn4.y), hnb = pack2(hn4.z, hn4.w);
            const int j = 2 * jj;
            hb2[j]     = clip2(fma2(vv, hpa, hb2[j]));
            prA = fma2(hna, fma2(av2[j], hb2[j], wv2[j]), prA);
            hb2[j + 1] = clip2(fma2(vv, hpb, hb2[j + 1]));
            prB = fma2(hnb, fma2(av2[j + 1], hb2[j + 1], wv2[j + 1]), prB);
        }

        if (step < kT - 1) {
            float pa, pb, pc, pd;
            unpack2(prA, pa, pb);
            unpack2(prB, pc, pd);
            const float pr = (pa + pb) + (pc + pd);
            const int np = par ^ 1;
            // push partial to self + 3 peers
            recv[np][c][t] = pr;
            st_cluster_f32(pr_addr[np][0], pr);
            st_cluster_f32(pr_addr[np][1], pr);
            st_cluster_f32(pr_addr[np][2], pr);
            __syncthreads();                 // all CTA pushes done
            if (t == 0) {                    // one release-arrive per target CTA
                mbar_arrive_rel_cluster(mb_addr[np][0]);
                mbar_arrive_rel_cluster(mb_addr[np][1]);
                mbar_arrive_rel_cluster(mb_addr[np][2]);
                mbar_arrive_rel_cluster(mb_addr[np][3]);
            }
            mbar_wait_acq_cluster(smem_u32(&mbar[np]), (unsigned)((step >> 1) & 1));
            const float hsum = (recv[np][0][t] + recv[np][1][t]) +
                               (recv[np][2][t] + recv[np][3][t]);
            h_cur = tanhf(xw_next + hsum);
        }
    }

    // ---- final outputs ----
    if (c == 0) hf[b * kH + t] = h_cur;    // h at step T-1
#pragma unroll
    for (int j = 0; j < 32; ++j) {
        float lo, hi;
        unpack2(hb2[j], lo, hi);
        hebbf[(size_t)b * kH * kH + (i0 + 2 * j) * kH + t] = lo;
        hebbf[(size_t)b * kH * kH + (i0 + 2 * j + 1) * kH + t] = hi;
    }
}

// ---------------------------------------------------------------------------
extern "C" void kernel_launch(void* const* d_in, const int* in_sizes, int n_in,
                              void* d_out, int out_size) {
    const float* x     = (const float*)d_in[0];
    const float* Wi    = (const float*)d_in[1];
    const float* bi    = (const float*)d_in[2];
    const float* w     = (const float*)d_in[3];
    const float* alpha = (const float*)d_in[4];
    const float* Wm    = (const float*)d_in[5];
    const float* bm    = (const float*)d_in[6];
    const float* Wf    = (const float*)d_in[7];
    const float* bf    = (const float*)d_in[8];
    float* out = (float*)d_out;

    xwi_kernel<<<kT * kB, kThreads>>>(x, Wi, bi);
    plastic_kernel<<<kNCTA, kThreads>>>(w, alpha, Wm, bm, Wf, bf, out);
}

// round 7
// speedup vs baseline: 1.3698x; 1.3698x over previous
#include <cuda_runtime.h>

// PlasticNet: T=64 steps, B=32, I=128, H=256, clip=2.0
// out = [ ys (T*B*H) | h_f (B*H) | hebb_f (B*H*H) ]  float32
//
// 32 clusters of 4 CTAs (one per sample). CTA c owns presynaptic rows
// [c*64, c*64+64). Thread t owns column t: 64 hebb/w/alpha scalars in regs,
// packed as 32 f32x2 pairs (fma.rn.f32x2; clip scalar on the halves).
// Per step: push 256-wide rec partials into peers' SMEM (DSMEM), then one
// hardware cluster barrier (arrive/wait split) orders delivery.

static constexpr int kT = 64;
static constexpr int kB = 32;
static constexpr int kI = 128;
static constexpr int kH = 256;
static constexpr int kRows = 64;
static constexpr int kNCTA = kB * 4;
static constexpr int kThreads = 256;

typedef unsigned long long ull;

__device__ float g_xwi[kT * kB * kH];              // x@Wi + bi, precomputed

// ---------------------------------------------------------------------------
__global__ void xwi_kernel(const float* __restrict__ x,
                           const float* __restrict__ Wi,
                           const float* __restrict__ bi) {
    __shared__ float xs[kI];
    const int row = blockIdx.x;        // 0 .. T*B-1
    const int k = threadIdx.x;         // 0 .. 255
    if (k < kI) xs[k] = x[row * kI + k];
    __syncthreads();
    float acc = bi[k];
#pragma unroll 16
    for (int i = 0; i < kI; ++i)
        acc = fmaf(xs[i], Wi[i * kH + k], acc);
    g_xwi[row * kH + k] = acc;
}

// ---------------------------------------------------------------------------
// PTX helpers
// ---------------------------------------------------------------------------
__device__ __forceinline__ unsigned smem_u32(const void* p) {
    return (unsigned)__cvta_generic_to_shared(p);
}
__device__ __forceinline__ unsigned mapa_u32(unsigned addr, unsigned rank) {
    unsigned o;
    asm("mapa.shared::cluster.u32 %0, %1, %2;" : "=r"(o) : "r"(addr), "r"(rank));
    return o;
}
__device__ __forceinline__ void st_cluster_f32(unsigned addr, float v) {
    asm volatile("st.shared::cluster.f32 [%0], %1;" :: "r"(addr), "f"(v) : "memory");
}
__device__ __forceinline__ void cluster_arrive() {
    asm volatile("barrier.cluster.arrive.aligned;" ::: "memory");
}
__device__ __forceinline__ void cluster_wait() {
    asm volatile("barrier.cluster.wait.aligned;" ::: "memory");
}

// ---- f32x2 packed math (PTX has fma/add/mul only; clip done on halves) ----
__device__ __forceinline__ ull pack2(float lo, float hi) {
    ull r; asm("mov.b64 %0, {%1, %2};" : "=l"(r) : "f"(lo), "f"(hi)); return r;
}
__device__ __forceinline__ void unpack2(ull v, float& lo, float& hi) {
    asm("mov.b64 {%0, %1}, %2;" : "=f"(lo), "=f"(hi) : "l"(v));
}
__device__ __forceinline__ ull fma2(ull a, ull b, ull c) {
    ull d; asm("fma.rn.f32x2 %0, %1, %2, %3;" : "=l"(d) : "l"(a), "l"(b), "l"(c));
    return d;
}
__device__ __forceinline__ ull clip2(ull v) {
    float lo, hi;
    unpack2(v, lo, hi);
    lo = fminf(fmaxf(lo, -2.f), 2.f);
    hi = fminf(fmaxf(hi, -2.f), 2.f);
    return pack2(lo, hi);
}

// ---------------------------------------------------------------------------
__global__ void __launch_bounds__(kThreads, 1) __cluster_dims__(4, 1, 1)
plastic_kernel(const float* __restrict__ w,
               const float* __restrict__ alpha,
               const float* __restrict__ Wm,
               const float* __restrict__ bm,
               const float* __restrict__ Wf,
               const float* __restrict__ bf,
               float* __restrict__ out) {
    const int b = blockIdx.x >> 2;
    const int c = blockIdx.x & 3;      // cluster ctarank
    const int t = threadIdx.x;
    const int lane = t & 31;
    const int wid = t >> 5;
    const int i0 = c * kRows;

    // Register state, packed by presynaptic-row pairs: pair j = rows i0+2j, i0+2j+1
    ull wv2[32], av2[32], hb2[32];
#pragma unroll
    for (int j = 0; j < 32; ++j) {
        wv2[j] = pack2(__ldg(&w[(i0 + 2 * j) * kH + t]),
                       __ldg(&w[(i0 + 2 * j + 1) * kH + t]));
        av2[j] = pack2(__ldg(&alpha[(i0 + 2 * j) * kH + t]),
                       __ldg(&alpha[(i0 + 2 * j + 1) * kH + t]));
        hb2[j] = 0ull;
    }
    const float wf_t = __ldg(&Wf[t]);
    const float bf_t = __ldg(&bf[t]);
    const float wm_t = __ldg(&Wm[t]);
    const float bm0 = __ldg(&bm[0]);

    __shared__ __align__(16) float hbuf[2][kH];       // h double buffer
    __shared__ __align__(16) float recv[2][4][kH];    // cluster partials, dbl buf
    __shared__ __align__(16) float wpart[8];          // per-warp eta partials

    hbuf[0][t] = 0.f;   // h_{-1} = 0
    __syncthreads();
    cluster_arrive();   // peers' smem live before any remote store
    cluster_wait();

    // DSMEM push addresses for the 3 peers (both parities)
    unsigned pr_addr[2][3];
#pragma unroll
    for (int p = 0; p < 2; ++p) {
        const unsigned lr = smem_u32(&recv[p][c][t]);
#pragma unroll
        for (int d = 1; d < 4; ++d)
            pr_addr[p][d - 1] = mapa_u32(lr, (unsigned)((c + d) & 3));
    }

    float* __restrict__ ys = out;
    float* __restrict__ hf = out + kT * kB * kH;
    float* __restrict__ hebbf = out + kT * kB * kH + kB * kH;

    // step 0: h_{-1}=0 -> rec=0 -> h = tanh(xwi[0])
    float h_cur = tanhf(__ldg(&g_xwi[b * kH + t]));

    for (int step = 0; step < kT; ++step) {
        const int par = step & 1;
        const float* __restrict__ hp = hbuf[par];        // h_{step-1}
        float* __restrict__ hn = hbuf[par ^ 1];          // h_step

        // prefetch next step's xwi early (hides L2 latency under the sweep)
        float xw_next = 0.f;
        if (step < kT - 1)
            xw_next = __ldg(&g_xwi[((step + 1) * kB + b) * kH + t]);

        hn[t] = h_cur;
        // eta partial: warp-level reduce of h.Wm, pre-sync
        float s = h_cur * wm_t;
#pragma unroll
        for (int off = 16; off; off >>= 1)
            s += __shfl_xor_sync(0xffffffffu, s, off);
        if (lane == 0) wpart[wid] = s;
        if (c == 0) ys[(step * kB + b) * kH + t] = h_cur;
        __syncthreads();

        // ---- eta = tanh(h . Wm + bm) ----
        const float4 wp0 = *reinterpret_cast<const float4*>(&wpart[0]);
        const float4 wp1 = *reinterpret_cast<const float4*>(&wpart[4]);
        const float eta = tanhf(((wp0.x + wp0.y) + (wp0.z + wp0.w)) +
                                ((wp1.x + wp1.y) + (wp1.z + wp1.w)) + bm0);
        const float v = fmaf(eta, wf_t, bf_t) * h_cur;    // me_t * h_t
        const ull vv = pack2(v, v);

        // ---- fused sweep: hebb = clip(hebb + v*hp), pr += hn*(w + a*hebb) ----
        ull prA = 0ull, prB = 0ull;
#pragma unroll
        for (int jj = 0; jj < 16; ++jj) {
            const float4 hp4 = *reinterpret_cast<const float4*>(&hp[i0 + 4 * jj]);
            const float4 hn4 = *reinterpret_cast<const float4*>(&hn[i0 + 4 * jj]);
            const ull hpa = pack2(hp4.x, hp4.y), hpb = pack2(hp4.z, hp4.w);
            const ull hna = pack2(hn4.x, hn4.y), hnb = pack2(hn4.z, hn4.w);
            const int j = 2 * jj;
            hb2[j]     = clip2(fma2(vv, hpa, hb2[j]));
            prA = fma2(hna, fma2(av2[j], hb2[j], wv2[j]), prA);
            hb2[j + 1] = clip2(fma2(vv, hpb, hb2[j + 1]));
            prB = fma2(hnb, fma2(av2[j + 1], hb2[j + 1], wv2[j + 1]), prB);
        }

        if (step < kT - 1) {
            float pa, pb, pc, pd;
            unpack2(prA, pa, pb);
            unpack2(prB, pc, pd);
            const float pr = (pa + pb) + (pc + pd);
            const int np = par ^ 1;
            // push partial to self + 3 peers
            recv[np][c][t] = pr;
            st_cluster_f32(pr_addr[np][0], pr);
            st_cluster_f32(pr_addr[np][1], pr);
            st_cluster_f32(pr_addr[np][2], pr);
            // hardware cluster barrier; arrive's release orders the pushes
            cluster_arrive();
            cluster_wait();
            const float hsum = (recv[np][0][t] + recv[np][1][t]) +
                               (recv[np][2][t] + recv[np][3][t]);
            h_cur = tanhf(xw_next + hsum);
        }
    }

    // ---- final outputs ----
    if (c == 0) hf[b * kH + t] = h_cur;    // h at step T-1
#pragma unroll
    for (int j = 0; j < 32; ++j) {
        float lo, hi;
        unpack2(hb2[j], lo, hi);
        hebbf[(size_t)b * kH * kH + (i0 + 2 * j) * kH + t] = lo;
        hebbf[(size_t)b * kH * kH + (i0 + 2 * j + 1) * kH + t] = hi;
    }
}

// ---------------------------------------------------------------------------
extern "C" void kernel_launch(void* const* d_in, const int* in_sizes, int n_in,
                              void* d_out, int out_size) {
    const float* x     = (const float*)d_in[0];
    const float* Wi    = (const float*)d_in[1];
    const float* bi    = (const float*)d_in[2];
    const float* w     = (const float*)d_in[3];
    const float* alpha = (const float*)d_in[4];
    const float* Wm    = (const float*)d_in[5];
    const float* bm    = (const float*)d_in[6];
    const float* Wf    = (const float*)d_in[7];
    const float* bf    = (const float*)d_in[8];
    float* out = (float*)d_out;

    xwi_kernel<<<kT * kB, kThreads>>>(x, Wi, bi);
    plastic_kernel<<<kNCTA, kThreads>>>(w, alpha, Wm, bm, Wf, bf, out);
}